// round 4
// baseline (speedup 1.0000x reference)
#include <cuda_runtime.h>
#include <math.h>
#include <stdint.h>

// Problem shape (fixed)
#define BB 4
#define SS 2048
#define DD 1024
#define MM (BB*SS)   // 8192

// ---------------- scratch ----------------
__device__ float g_X [MM*DD];                 // x, tf32-rounded
__device__ float g_Wq[DD*DD];
__device__ float g_Wk[DD*DD];
__device__ float g_Wv[DD*DD];
__device__ float g_Wo[DD*DD];
__device__ float g_Q [MM*DD];
__device__ float g_K [MM*DD];
__device__ float g_Vt[MM*DD];                 // V projected, transposed per batch: [b][d][s]
__device__ float g_S [(long long)BB*SS*SS];   // scores / probs
__device__ float g_A [MM*DD];

// ---------------- helpers ----------------
__device__ __forceinline__ uint32_t smem_u32(const void* p) {
    uint32_t a;
    asm("{ .reg .u64 t; cvta.to.shared.u64 t, %1; cvt.u32.u64 %0, t; }" : "=r"(a) : "l"(p));
    return a;
}
__device__ __forceinline__ void cp16(uint32_t dst, const void* src) {
    asm volatile("cp.async.cg.shared.global [%0], [%1], 16;" :: "r"(dst), "l"(src));
}
#define CP_COMMIT() asm volatile("cp.async.commit_group;" ::: "memory")
#define CP_WAIT1()  asm volatile("cp.async.wait_group 1;"  ::: "memory")

__device__ __forceinline__ float tf32rf(float x) {   // round-to-nearest tf32 (fp32 container)
    float r;
    asm("cvt.rna.tf32.f32 %0, %1;" : "=f"(r) : "f"(x));
    return r;
}

// chunk-swizzled smem offset: row stride 64B (16 floats), 16B chunk rotated by row>>1
#define SWOFF(row, c) ((uint32_t)((row)*64 + ((((c) + ((row)>>1)) & 3) << 4)))

__device__ __forceinline__ uint32_t lds_bits(const char* p, int row, int c, int w) {
    return ((const uint32_t*)(p + SWOFF(row, c)))[w];   // data already tf32-rounded
}

#define MMA_TF32(cc, aa, bb) \
    asm volatile("mma.sync.aligned.m16n8k8.row.col.f32.tf32.tf32.f32 " \
        "{%0,%1,%2,%3}, {%4,%5,%6,%7}, {%8,%9}, {%0,%1,%2,%3};" \
        : "+f"((cc)[0]), "+f"((cc)[1]), "+f"((cc)[2]), "+f"((cc)[3]) \
        : "r"((aa)[0]), "r"((aa)[1]), "r"((aa)[2]), "r"((aa)[3]), \
          "r"((bb)[0]), "r"((bb)[1]))

// ================= pre-round x and all weights to tf32 =================
#define NX4 (MM*DD/4)      // 2097152
#define NW4 (DD*DD/4)      // 262144
__global__ void __launch_bounds__(256) preround_all(
    const float4* __restrict__ x,
    const float4* __restrict__ wq, const float4* __restrict__ wk,
    const float4* __restrict__ wv, const float4* __restrict__ wo,
    float4* __restrict__ dx,
    float4* __restrict__ dwq, float4* __restrict__ dwk,
    float4* __restrict__ dwv, float4* __restrict__ dwo)
{
    long long i = (long long)blockIdx.x * blockDim.x + threadIdx.x;
    const float4* s; float4* d; long long off;
    if (i < NX4) { s = x; d = dx; off = i; }
    else {
        long long j = i - NX4;
        int seg = (int)(j / NW4);
        off = j % NW4;
        s = seg == 0 ? wq : seg == 1 ? wk : seg == 2 ? wv : wo;
        d = seg == 0 ? dwq : seg == 1 ? dwk : seg == 2 ? dwv : dwo;
    }
    float4 v = s[off];
    v.x = tf32rf(v.x); v.y = tf32rf(v.y); v.z = tf32rf(v.z); v.w = tf32rf(v.w);
    d[off] = v;
}

// ================= tf32 mma.sync GEMM: C = alpha * A @ B^T (TN) =================
// All operands pre-rounded to tf32 in memory. 128x128 CTA tile, BK=16,
// 3-stage cp.async, 128 threads = 4 warps (2x2), warp tile 64x64.
// mode: 0 plain | 1 causal tile-skip | 2 causal K-trunc + round out | 3 transposed+rounded out
#define STAGE 16384           // A 8KB + B 8KB
#define SM_TOTAL (3*STAGE)    // 49152

__global__ void __launch_bounds__(128, 2) gemm_mma(
    const float* __restrict__ A, const float* __restrict__ B, float* __restrict__ C,
    int M, int N, int K,
    long long sA, long long sB, long long sC,
    float alpha, int mode)
{
    extern __shared__ char smem[];
    int bz = blockIdx.z;
    const float* Ab = A + (long long)bz * sA;
    const float* Bb = B + (long long)bz * sB;

    int m0 = blockIdx.y * 128;
    int n0 = blockIdx.x * 128;
    if (mode == 1 && n0 >= m0 + 128) return;
    int Keff  = (mode == 2) ? min(K, m0 + 128) : K;
    int nIter = Keff >> 4;

    int tid = threadIdx.x, wid = tid >> 5, lane = tid & 31;
    int warp_m = wid >> 1, warp_n = wid & 1;
    int g = lane >> 2, w = lane & 3;
    uint32_t sb = smem_u32(smem);

    // global->smem: thread tid owns row tid (all 4 chunks of its 16-float row slice)
    uint32_t dOff[4];
    #pragma unroll
    for (int c = 0; c < 4; c++) dOff[c] = SWOFF(tid, c);
    const float* gAp = Ab + (long long)(m0 + tid) * K;
    const float* gBp = Bb + (long long)(n0 + tid) * K;

    float acc[4][8][4];
    #pragma unroll
    for (int i = 0; i < 4; i++)
        #pragma unroll
        for (int j = 0; j < 8; j++)
            #pragma unroll
            for (int q = 0; q < 4; q++) acc[i][j][q] = 0.f;

    #pragma unroll
    for (int s = 0; s < 2; s++) {
        uint32_t base = sb + s * STAGE;
        int k0 = s * 16;
        #pragma unroll
        for (int c = 0; c < 4; c++) cp16(base + dOff[c], gAp + k0 + c * 4);
        #pragma unroll
        for (int c = 0; c < 4; c++) cp16(base + 8192 + dOff[c], gBp + k0 + c * 4);
        CP_COMMIT();
    }

    for (int kt = 0; kt < nIter; kt++) {
        CP_WAIT1();
        __syncthreads();

        const char* pA = smem + (kt % 3) * STAGE;
        const char* pB = pA + 8192;
        #pragma unroll
        for (int ks = 0; ks < 2; ks++) {
            uint32_t af[4][4], bf[8][2];
            #pragma unroll
            for (int mf = 0; mf < 4; mf++) {
                int r = warp_m * 64 + mf * 16 + g;
                af[mf][0] = lds_bits(pA, r,     ks*2,     w);
                af[mf][1] = lds_bits(pA, r + 8, ks*2,     w);
                af[mf][2] = lds_bits(pA, r,     ks*2 + 1, w);
                af[mf][3] = lds_bits(pA, r + 8, ks*2 + 1, w);
            }
            #pragma unroll
            for (int nf = 0; nf < 8; nf++) {
                int nr = warp_n * 64 + nf * 8 + g;
                bf[nf][0] = lds_bits(pB, nr, ks*2,     w);
                bf[nf][1] = lds_bits(pB, nr, ks*2 + 1, w);
            }
            #pragma unroll
            for (int mf = 0; mf < 4; mf++)
                #pragma unroll
                for (int nf = 0; nf < 8; nf++)
                    MMA_TF32(acc[mf][nf], af[mf], bf[nf]);
        }

        int nk = kt + 2;
        if (nk < nIter) {
            uint32_t base = sb + (nk % 3) * STAGE;
            int k0 = nk * 16;
            #pragma unroll
            for (int c = 0; c < 4; c++) cp16(base + dOff[c], gAp + k0 + c * 4);
            #pragma unroll
            for (int c = 0; c < 4; c++) cp16(base + 8192 + dOff[c], gBp + k0 + c * 4);
        }
        CP_COMMIT();
    }

    if (mode != 3) {
        bool rnd = (mode == 2);
        float* Cb = C + (long long)bz * sC;
        #pragma unroll
        for (int mf = 0; mf < 4; mf++) {
            int r0 = m0 + warp_m * 64 + mf * 16 + g;
            #pragma unroll
            for (int nf = 0; nf < 8; nf++) {
                int col = n0 + warp_n * 64 + nf * 8 + w * 2;
                float2 v0 = make_float2(acc[mf][nf][0] * alpha, acc[mf][nf][1] * alpha);
                float2 v1 = make_float2(acc[mf][nf][2] * alpha, acc[mf][nf][3] * alpha);
                if (rnd) {
                    v0.x = tf32rf(v0.x); v0.y = tf32rf(v0.y);
                    v1.x = tf32rf(v1.x); v1.y = tf32rf(v1.y);
                }
                *(float2*)&Cb[(long long)r0 * N + col]       = v0;
                *(float2*)&Cb[(long long)(r0 + 8) * N + col] = v1;
            }
        }
    } else {
        // transposed epilogue: stage 128 rows x 64 cols through smem, store d-major, rounded
        float* Ts = (float*)smem;                 // [128][65]
        int b = m0 / SS;
        int srow0 = m0 % SS;
        float* Cb = C + (long long)b * sC;        // sC = DD*SS
        #pragma unroll
        for (int nc = 0; nc < 2; nc++) {
            __syncthreads();
            if (warp_n == nc) {
                #pragma unroll
                for (int mf = 0; mf < 4; mf++) {
                    int mloc = warp_m * 64 + mf * 16 + g;
                    #pragma unroll
                    for (int nf = 0; nf < 8; nf++) {
                        int d = nf * 8 + w * 2;
                        Ts[mloc * 65 + d]           = acc[mf][nf][0];
                        Ts[mloc * 65 + d + 1]       = acc[mf][nf][1];
                        Ts[(mloc + 8) * 65 + d]     = acc[mf][nf][2];
                        Ts[(mloc + 8) * 65 + d + 1] = acc[mf][nf][3];
                    }
                }
            }
            __syncthreads();
            int col = tid >> 1, half = tid & 1;   // 64 cols, 2 threads per col
            #pragma unroll
            for (int j = 0; j < 16; j++) {
                int r = half * 64 + j * 4;
                float4 v;
                v.x = tf32rf(Ts[(r + 0) * 65 + col]);
                v.y = tf32rf(Ts[(r + 1) * 65 + col]);
                v.z = tf32rf(Ts[(r + 2) * 65 + col]);
                v.w = tf32rf(Ts[(r + 3) * 65 + col]);
                *(float4*)&Cb[(long long)(n0 + nc * 64 + col) * SS + srow0 + r] = v;
            }
        }
    }
}

// ================= RoPE (fp32, in-place, writes tf32-rounded) =================
__global__ void rope_kernel(float* __restrict__ Q, float* __restrict__ Kt,
                            const int* __restrict__ pos32)
{
    long long idx = (long long)blockIdx.x * blockDim.x + threadIdx.x;
    const int half = DD / 2;
    long long total = (long long)BB * SS * half;
    if (idx >= total) return;

    int i = (int)(idx % half);
    long long row = idx / half;
    bool is64 = (pos32[1] == 0);              // int64 vs int32 positions
    int p = is64 ? pos32[2 * row] : pos32[row];

    float fexp = (float)(2 * i) / (float)DD;
    float inv_freq = exp2f(-fexp * 13.28771238f);   // log2(10000)
    float ang = (float)p * inv_freq;
    float c, sn;
    sincosf(ang, &sn, &c);

    long long off = row * DD + 2 * i;
    float q1 = Q[off], q2 = Q[off + 1];
    Q[off]     = tf32rf(q1 * c - q2 * sn);
    Q[off + 1] = tf32rf(q1 * sn + q2 * c);
    float k1 = Kt[off], k2 = Kt[off + 1];
    Kt[off]     = tf32rf(k1 * c - k2 * sn);
    Kt[off + 1] = tf32rf(k1 * sn + k2 * c);
}

// ================= causal softmax (in place, tf32-rounded probs, zero tail) =================
__device__ __forceinline__ float warpMax(float v) {
    #pragma unroll
    for (int o = 16; o; o >>= 1) v = fmaxf(v, __shfl_xor_sync(0xffffffffu, v, o));
    return v;
}
__device__ __forceinline__ float warpSum(float v) {
    #pragma unroll
    for (int o = 16; o; o >>= 1) v += __shfl_xor_sync(0xffffffffu, v, o);
    return v;
}

__global__ void __launch_bounds__(256) softmax_causal(float* __restrict__ Sc)
{
    int q = blockIdx.x;
    int b = blockIdx.y;
    float* row = Sc + ((long long)b * SS + q) * SS;
    int L = q + 1;
    int tid = threadIdx.x, warp = tid >> 5, lane = tid & 31;
    __shared__ float red[8];

    float m = -1e30f;
    for (int j = tid; j < L; j += 256) m = fmaxf(m, row[j]);
    m = warpMax(m);
    if (lane == 0) red[warp] = m;
    __syncthreads();
    m = (lane < 8) ? red[lane] : -1e30f;
    m = warpMax(m);
    m = __shfl_sync(0xffffffffu, m, 0);

    float sum = 0.f;
    for (int j = tid; j < L; j += 256) {
        float e = __expf(row[j] - m);
        row[j] = e;
        sum += e;
    }
    sum = warpSum(sum);
    __syncthreads();
    if (lane == 0) red[warp] = sum;
    __syncthreads();
    sum = (lane < 8) ? red[lane] : 0.f;
    sum = warpSum(sum);
    sum = __shfl_sync(0xffffffffu, sum, 0);
    float inv = 1.f / sum;

    for (int j = tid; j < L; j += 256) row[j] = tf32rf(row[j] * inv);
    for (int j = L + tid; j < SS; j += 256) row[j] = 0.f;
}

// ================= launch =================
extern "C" void kernel_launch(void* const* d_in, const int* in_sizes, int n_in,
                              void* d_out, int out_size)
{
    const float* x   = (const float*)d_in[0];
    const float* Wq  = (const float*)d_in[1];
    const float* Wk  = (const float*)d_in[2];
    const float* Wv  = (const float*)d_in[3];
    const float* Wo  = (const float*)d_in[4];
    const int*   pos = (const int*)d_in[5];
    float* out = (float*)d_out;

    static float *pX=nullptr,*pWq,*pWk,*pWv,*pWo,*pQ,*pK,*pVt,*pS,*pA;
    static bool inited = false;
    if (!inited) {
        cudaGetSymbolAddress((void**)&pX,  g_X);
        cudaGetSymbolAddress((void**)&pWq, g_Wq);
        cudaGetSymbolAddress((void**)&pWk, g_Wk);
        cudaGetSymbolAddress((void**)&pWv, g_Wv);
        cudaGetSymbolAddress((void**)&pWo, g_Wo);
        cudaGetSymbolAddress((void**)&pQ,  g_Q);
        cudaGetSymbolAddress((void**)&pK,  g_K);
        cudaGetSymbolAddress((void**)&pVt, g_Vt);
        cudaGetSymbolAddress((void**)&pS,  g_S);
        cudaGetSymbolAddress((void**)&pA,  g_A);
        cudaFuncSetAttribute(gemm_mma, cudaFuncAttributeMaxDynamicSharedMemorySize, SM_TOTAL);
        inited = true;
    }

    // 1) pre-round x and weights to tf32 (one fused launch)
    long long tot4 = NX4 + 4LL * NW4;
    preround_all<<<(unsigned)((tot4 + 255) / 256), 256>>>(
        (const float4*)x, (const float4*)Wq, (const float4*)Wk, (const float4*)Wv, (const float4*)Wo,
        (float4*)pX, (float4*)pWq, (float4*)pWk, (float4*)pWv, (float4*)pWo);

    dim3 blk(128);
    dim3 gProj(DD / 128, MM / 128, 1);      // (8, 64)

    // 2-4) projections
    gemm_mma<<<gProj, blk, SM_TOTAL>>>(pX, pWq, pQ, MM, DD, DD, 0, 0, 0, 1.f, 0);
    gemm_mma<<<gProj, blk, SM_TOTAL>>>(pX, pWk, pK, MM, DD, DD, 0, 0, 0, 1.f, 0);
    gemm_mma<<<gProj, blk, SM_TOTAL>>>(pX, pWv, pVt, MM, DD, DD, 0, 0, (long long)DD * SS, 1.f, 3);

    // 5) RoPE on Q and K (rounds outputs)
    long long ropeThreads = (long long)BB * SS * (DD / 2);
    rope_kernel<<<(unsigned)((ropeThreads + 255) / 256), 256>>>(pQ, pK, pos);

    // 6) scores = Q @ K^T / 32  (this is the launch ncu captures)
    dim3 gS(SS / 128, SS / 128, BB);        // (16, 16, 4)
    gemm_mma<<<gS, blk, SM_TOTAL>>>(pQ, pK, pS, SS, SS, DD,
                                    (long long)SS * DD, (long long)SS * DD, (long long)SS * SS,
                                    0.03125f, 1);

    // 7) causal softmax (rounds probs, zero-fills above diagonal)
    softmax_causal<<<dim3(SS, BB), 256>>>(pS);

    // 8) attn = P @ Vt^T (K-trunc at diagonal, rounded output)
    dim3 gPV(DD / 128, SS / 128, BB);       // (8, 16, 4)
    gemm_mma<<<gPV, blk, SM_TOTAL>>>(pS, pVt, pA, SS, DD, SS,
                                     (long long)SS * SS, (long long)DD * SS, (long long)SS * DD,
                                     1.f, 2);

    // 9) out = attn @ Wo^T (full fp32 output)
    gemm_mma<<<gProj, blk, SM_TOTAL>>>(pA, pWo, out, MM, DD, DD, 0, 0, 0, 1.f, 0);
}

// round 5
// speedup vs baseline: 1.4205x; 1.4205x over previous
#include <cuda_runtime.h>
#include <math.h>
#include <stdint.h>

// Problem shape (fixed)
#define BB 4
#define SS 2048
#define DD 1024
#define MM (BB*SS)   // 8192

// ---------------- scratch ----------------
__device__ float g_X [MM*DD];                 // x, tf32-rounded
__device__ float g_Wq[DD*DD];
__device__ float g_Wk[DD*DD];
__device__ float g_Wv[DD*DD];
__device__ float g_Wo[DD*DD];
__device__ float g_Q [MM*DD];
__device__ float g_K [MM*DD];
__device__ float g_Vt[MM*DD];                 // V projected, transposed per batch: [b][d][s]
__device__ float g_S [(long long)BB*SS*SS];   // scores / probs
__device__ float g_A [MM*DD];

// ---------------- helpers ----------------
__device__ __forceinline__ uint32_t smem_u32(const void* p) {
    uint32_t a;
    asm("{ .reg .u64 t; cvta.to.shared.u64 t, %1; cvt.u32.u64 %0, t; }" : "=r"(a) : "l"(p));
    return a;
}
__device__ __forceinline__ void cp16(uint32_t dst, const void* src) {
    asm volatile("cp.async.cg.shared.global [%0], [%1], 16;" :: "r"(dst), "l"(src));
}
#define CP_COMMIT() asm volatile("cp.async.commit_group;" ::: "memory")
#define CP_WAIT1()  asm volatile("cp.async.wait_group 1;"  ::: "memory")

__device__ __forceinline__ float tf32rf(float x) {   // round-to-nearest tf32 (fp32 container)
    float r;
    asm("cvt.rna.tf32.f32 %0, %1;" : "=f"(r) : "f"(x));
    return r;
}

// chunk-swizzled smem offset: row stride 64B (16 floats), 16B chunk rotated by row>>1
#define SWOFF(row, c) ((uint32_t)((row)*64 + ((((c) + ((row)>>1)) & 3) << 4)))

__device__ __forceinline__ uint32_t lds_bits(const char* p, int row, int c, int w) {
    return ((const uint32_t*)(p + SWOFF(row, c)))[w];   // data already tf32-rounded
}

#define MMA_TF32(cc, aa, bb) \
    asm volatile("mma.sync.aligned.m16n8k8.row.col.f32.tf32.tf32.f32 " \
        "{%0,%1,%2,%3}, {%4,%5,%6,%7}, {%8,%9}, {%0,%1,%2,%3};" \
        : "+f"((cc)[0]), "+f"((cc)[1]), "+f"((cc)[2]), "+f"((cc)[3]) \
        : "r"((aa)[0]), "r"((aa)[1]), "r"((aa)[2]), "r"((aa)[3]), \
          "r"((bb)[0]), "r"((bb)[1]))

// ================= pre-round x and all weights to tf32 =================
#define NX4 (MM*DD/4)      // 2097152
#define NW4 (DD*DD/4)      // 262144
__global__ void __launch_bounds__(256) preround_all(
    const float4* __restrict__ x,
    const float4* __restrict__ wq, const float4* __restrict__ wk,
    const float4* __restrict__ wv, const float4* __restrict__ wo,
    float4* __restrict__ dx,
    float4* __restrict__ dwq, float4* __restrict__ dwk,
    float4* __restrict__ dwv, float4* __restrict__ dwo)
{
    long long i = (long long)blockIdx.x * blockDim.x + threadIdx.x;
    const float4* s; float4* d; long long off;
    if (i < NX4) { s = x; d = dx; off = i; }
    else {
        long long j = i - NX4;
        int seg = (int)(j / NW4);
        off = j % NW4;
        s = seg == 0 ? wq : seg == 1 ? wk : seg == 2 ? wv : wo;
        d = seg == 0 ? dwq : seg == 1 ? dwk : seg == 2 ? dwv : dwo;
    }
    float4 v = s[off];
    v.x = tf32rf(v.x); v.y = tf32rf(v.y); v.z = tf32rf(v.z); v.w = tf32rf(v.w);
    d[off] = v;
}

// ================= tf32 mma.sync GEMM: C = alpha * A @ B^T (TN) =================
// Operands pre-rounded to tf32 in memory (no CVT in inner loop).
// 128x128 CTA tile, BK=16, 3-stage cp.async, 256 threads = 8 warps (2x4),
// warp tile 64x32. mode: 0 plain | 1 causal tile-skip | 2 causal K-trunc + round out
//                       | 3 transposed-per-batch + rounded out
#define STAGE 16384           // A 8KB + B 8KB
#define SM_TOTAL (3*STAGE)    // 49152

__global__ void __launch_bounds__(256, 2) gemm_mma(
    const float* __restrict__ A, const float* __restrict__ B, float* __restrict__ C,
    int M, int N, int K,
    long long sA, long long sB, long long sC,
    float alpha, int mode)
{
    extern __shared__ char smem[];
    int bz = blockIdx.z;
    const float* Ab = A + (long long)bz * sA;
    const float* Bb = B + (long long)bz * sB;

    int m0 = blockIdx.y * 128;
    int n0 = blockIdx.x * 128;
    if (mode == 1 && n0 >= m0 + 128) return;
    int Keff  = (mode == 2) ? min(K, m0 + 128) : K;
    int nIter = Keff >> 4;

    int tid = threadIdx.x, wid = tid >> 5, lane = tid & 31;
    int warp_m = wid >> 2, warp_n = wid & 3;
    int g = lane >> 2, w = lane & 3;
    uint32_t sb = smem_u32(smem);

    // global->smem: thread -> row tid>>1, chunks (tid&1)*2, +1
    int rowL = tid >> 1, cL = (tid & 1) * 2;
    uint32_t dOff0 = SWOFF(rowL, cL);
    uint32_t dOff1 = SWOFF(rowL, cL + 1);
    const float* gAp = Ab + (long long)(m0 + rowL) * K + cL * 4;
    const float* gBp = Bb + (long long)(n0 + rowL) * K + cL * 4;

    float acc[4][4][4];
    #pragma unroll
    for (int i = 0; i < 4; i++)
        #pragma unroll
        for (int j = 0; j < 4; j++)
            #pragma unroll
            for (int q = 0; q < 4; q++) acc[i][j][q] = 0.f;

    #pragma unroll
    for (int s = 0; s < 2; s++) {
        uint32_t base = sb + s * STAGE;
        int k0 = s * 16;
        cp16(base + dOff0,        gAp + k0);
        cp16(base + dOff1,        gAp + k0 + 4);
        cp16(base + 8192 + dOff0, gBp + k0);
        cp16(base + 8192 + dOff1, gBp + k0 + 4);
        CP_COMMIT();
    }

    for (int kt = 0; kt < nIter; kt++) {
        CP_WAIT1();
        __syncthreads();

        const char* pA = smem + (kt % 3) * STAGE;
        const char* pB = pA + 8192;
        #pragma unroll
        for (int ks = 0; ks < 2; ks++) {
            uint32_t af[4][4], bf[4][2];
            #pragma unroll
            for (int mf = 0; mf < 4; mf++) {
                int r = warp_m * 64 + mf * 16 + g;
                af[mf][0] = lds_bits(pA, r,     ks*2,     w);
                af[mf][1] = lds_bits(pA, r + 8, ks*2,     w);
                af[mf][2] = lds_bits(pA, r,     ks*2 + 1, w);
                af[mf][3] = lds_bits(pA, r + 8, ks*2 + 1, w);
            }
            #pragma unroll
            for (int nf = 0; nf < 4; nf++) {
                int nr = warp_n * 32 + nf * 8 + g;
                bf[nf][0] = lds_bits(pB, nr, ks*2,     w);
                bf[nf][1] = lds_bits(pB, nr, ks*2 + 1, w);
            }
            #pragma unroll
            for (int mf = 0; mf < 4; mf++)
                #pragma unroll
                for (int nf = 0; nf < 4; nf++)
                    MMA_TF32(acc[mf][nf], af[mf], bf[nf]);
        }

        int nk = kt + 2;
        if (nk < nIter) {
            uint32_t base = sb + (nk % 3) * STAGE;
            int k0 = nk * 16;
            cp16(base + dOff0,        gAp + k0);
            cp16(base + dOff1,        gAp + k0 + 4);
            cp16(base + 8192 + dOff0, gBp + k0);
            cp16(base + 8192 + dOff1, gBp + k0 + 4);
        }
        CP_COMMIT();
    }

    if (mode != 3) {
        bool rnd = (mode == 2);
        float* Cb = C + (long long)bz * sC;
        #pragma unroll
        for (int mf = 0; mf < 4; mf++) {
            int r0 = m0 + warp_m * 64 + mf * 16 + g;
            #pragma unroll
            for (int nf = 0; nf < 4; nf++) {
                int col = n0 + warp_n * 32 + nf * 8 + w * 2;
                float2 v0 = make_float2(acc[mf][nf][0] * alpha, acc[mf][nf][1] * alpha);
                float2 v1 = make_float2(acc[mf][nf][2] * alpha, acc[mf][nf][3] * alpha);
                if (rnd) {
                    v0.x = tf32rf(v0.x); v0.y = tf32rf(v0.y);
                    v1.x = tf32rf(v1.x); v1.y = tf32rf(v1.y);
                }
                *(float2*)&Cb[(long long)r0 * N + col]       = v0;
                *(float2*)&Cb[(long long)(r0 + 8) * N + col] = v1;
            }
        }
    } else {
        // transposed epilogue: stage 128x32 column block through smem, store d-major, rounded
        float* Ts = (float*)smem;                 // [128][33]
        int b = m0 / SS;
        int srow0 = m0 % SS;
        float* Cb = C + (long long)b * sC;        // sC = DD*SS
        #pragma unroll
        for (int nc = 0; nc < 4; nc++) {
            __syncthreads();
            if (warp_n == nc) {
                #pragma unroll
                for (int mf = 0; mf < 4; mf++) {
                    int mloc = warp_m * 64 + mf * 16 + g;
                    #pragma unroll
                    for (int nf = 0; nf < 4; nf++) {
                        int d = nf * 8 + w * 2;
                        Ts[mloc * 33 + d]           = acc[mf][nf][0];
                        Ts[mloc * 33 + d + 1]       = acc[mf][nf][1];
                        Ts[(mloc + 8) * 33 + d]     = acc[mf][nf][2];
                        Ts[(mloc + 8) * 33 + d + 1] = acc[mf][nf][3];
                    }
                }
            }
            __syncthreads();
            #pragma unroll
            for (int dd = 0; dd < 4; dd++) {
                int d = wid * 4 + dd;
                float4 v;
                v.x = tf32rf(Ts[(lane * 4 + 0) * 33 + d]);
                v.y = tf32rf(Ts[(lane * 4 + 1) * 33 + d]);
                v.z = tf32rf(Ts[(lane * 4 + 2) * 33 + d]);
                v.w = tf32rf(Ts[(lane * 4 + 3) * 33 + d]);
                *(float4*)&Cb[(long long)(n0 + nc * 32 + d) * SS + srow0 + lane * 4] = v;
            }
        }
    }
}

// ================= RoPE (fp32, in-place, writes tf32-rounded) =================
__global__ void rope_kernel(float* __restrict__ Q, float* __restrict__ Kt,
                            const int* __restrict__ pos32)
{
    long long idx = (long long)blockIdx.x * blockDim.x + threadIdx.x;
    const int half = DD / 2;
    long long total = (long long)BB * SS * half;
    if (idx >= total) return;

    int i = (int)(idx % half);
    long long row = idx / half;
    bool is64 = (pos32[1] == 0);              // int64 vs int32 positions
    int p = is64 ? pos32[2 * row] : pos32[row];

    float fexp = (float)(2 * i) / (float)DD;
    float inv_freq = exp2f(-fexp * 13.28771238f);   // log2(10000)
    float ang = (float)p * inv_freq;
    float c, sn;
    sincosf(ang, &sn, &c);

    long long off = row * DD + 2 * i;
    float q1 = Q[off], q2 = Q[off + 1];
    Q[off]     = tf32rf(q1 * c - q2 * sn);
    Q[off + 1] = tf32rf(q1 * sn + q2 * c);
    float k1 = Kt[off], k2 = Kt[off + 1];
    Kt[off]     = tf32rf(k1 * c - k2 * sn);
    Kt[off + 1] = tf32rf(k1 * sn + k2 * c);
}

// ================= causal softmax (in place, tf32-rounded probs, zero tail) =================
__device__ __forceinline__ float warpMax(float v) {
    #pragma unroll
    for (int o = 16; o; o >>= 1) v = fmaxf(v, __shfl_xor_sync(0xffffffffu, v, o));
    return v;
}
__device__ __forceinline__ float warpSum(float v) {
    #pragma unroll
    for (int o = 16; o; o >>= 1) v += __shfl_xor_sync(0xffffffffu, v, o);
    return v;
}

__global__ void __launch_bounds__(256) softmax_causal(float* __restrict__ Sc)
{
    int q = blockIdx.x;
    int b = blockIdx.y;
    float* row = Sc + ((long long)b * SS + q) * SS;
    int L = q + 1;
    int tid = threadIdx.x, warp = tid >> 5, lane = tid & 31;
    __shared__ float red[8];

    float m = -1e30f;
    for (int j = tid; j < L; j += 256) m = fmaxf(m, row[j]);
    m = warpMax(m);
    if (lane == 0) red[warp] = m;
    __syncthreads();
    m = (lane < 8) ? red[lane] : -1e30f;
    m = warpMax(m);
    m = __shfl_sync(0xffffffffu, m, 0);

    float sum = 0.f;
    for (int j = tid; j < L; j += 256) {
        float e = __expf(row[j] - m);
        row[j] = e;
        sum += e;
    }
    sum = warpSum(sum);
    __syncthreads();
    if (lane == 0) red[warp] = sum;
    __syncthreads();
    sum = (lane < 8) ? red[lane] : 0.f;
    sum = warpSum(sum);
    sum = __shfl_sync(0xffffffffu, sum, 0);
    float inv = 1.f / sum;

    for (int j = tid; j < L; j += 256) row[j] = tf32rf(row[j] * inv);
    for (int j = L + tid; j < SS; j += 256) row[j] = 0.f;
}

// ================= launch =================
extern "C" void kernel_launch(void* const* d_in, const int* in_sizes, int n_in,
                              void* d_out, int out_size)
{
    const float* x   = (const float*)d_in[0];
    const float* Wq  = (const float*)d_in[1];
    const float* Wk  = (const float*)d_in[2];
    const float* Wv  = (const float*)d_in[3];
    const float* Wo  = (const float*)d_in[4];
    const int*   pos = (const int*)d_in[5];
    float* out = (float*)d_out;

    static float *pX=nullptr,*pWq,*pWk,*pWv,*pWo,*pQ,*pK,*pVt,*pS,*pA;
    static bool inited = false;
    if (!inited) {
        cudaGetSymbolAddress((void**)&pX,  g_X);
        cudaGetSymbolAddress((void**)&pWq, g_Wq);
        cudaGetSymbolAddress((void**)&pWk, g_Wk);
        cudaGetSymbolAddress((void**)&pWv, g_Wv);
        cudaGetSymbolAddress((void**)&pWo, g_Wo);
        cudaGetSymbolAddress((void**)&pQ,  g_Q);
        cudaGetSymbolAddress((void**)&pK,  g_K);
        cudaGetSymbolAddress((void**)&pVt, g_Vt);
        cudaGetSymbolAddress((void**)&pS,  g_S);
        cudaGetSymbolAddress((void**)&pA,  g_A);
        cudaFuncSetAttribute(gemm_mma, cudaFuncAttributeMaxDynamicSharedMemorySize, SM_TOTAL);
        inited = true;
    }

    // 1) pre-round x and weights to tf32
    long long tot4 = NX4 + 4LL * NW4;
    preround_all<<<(unsigned)((tot4 + 255) / 256), 256>>>(
        (const float4*)x, (const float4*)Wq, (const float4*)Wk, (const float4*)Wv, (const float4*)Wo,
        (float4*)pX, (float4*)pWq, (float4*)pWk, (float4*)pWv, (float4*)pWo);

    dim3 blk(256);
    dim3 gProj(DD / 128, MM / 128, 1);      // (8, 64)

    // 2-4) projections
    gemm_mma<<<gProj, blk, SM_TOTAL>>>(pX, pWq, pQ, MM, DD, DD, 0, 0, 0, 1.f, 0);
    gemm_mma<<<gProj, blk, SM_TOTAL>>>(pX, pWk, pK, MM, DD, DD, 0, 0, 0, 1.f, 0);
    gemm_mma<<<gProj, blk, SM_TOTAL>>>(pX, pWv, pVt, MM, DD, DD, 0, 0, (long long)DD * SS, 1.f, 3);

    // 5) RoPE on Q and K (rounds outputs)
    long long ropeThreads = (long long)BB * SS * (DD / 2);
    rope_kernel<<<(unsigned)((ropeThreads + 255) / 256), 256>>>(pQ, pK, pos);

    // 6) scores = Q @ K^T / 32 (captured by ncu)
    dim3 gS(SS / 128, SS / 128, BB);        // (16, 16, 4)
    gemm_mma<<<gS, blk, SM_TOTAL>>>(pQ, pK, pS, SS, SS, DD,
                                    (long long)SS * DD, (long long)SS * DD, (long long)SS * SS,
                                    0.03125f, 1);

    // 7) causal softmax (rounds probs, zero-fills above diagonal)
    softmax_causal<<<dim3(SS, BB), 256>>>(pS);

    // 8) attn = P @ Vt^T (K-trunc at diagonal, rounded output)
    dim3 gPV(DD / 128, SS / 128, BB);       // (8, 16, 4)
    gemm_mma<<<gPV, blk, SM_TOTAL>>>(pS, pVt, pA, SS, DD, SS,
                                     (long long)SS * SS, (long long)DD * SS, (long long)SS * DD,
                                     1.f, 2);

    // 9) out = attn @ Wo^T (full fp32 output)
    gemm_mma<<<gProj, blk, SM_TOTAL>>>(pA, pWo, out, MM, DD, DD, 0, 0, 0, 1.f, 0);
}